// round 9
// baseline (speedup 1.0000x reference)
#include <cuda_runtime.h>
#include <mma.h>
#include <cstdint>
#include <cstddef>

using namespace nvcuda;

constexpr int Tn  = 2048;
constexpr int Bn  = 2;
constexpr int En  = 1024;
constexpr int Hn  = 16;
constexpr int Mn  = Tn * Bn;   // 4096 rows for the projection GEMMs

// Scratch (allocation-free rule: __device__ globals)
__device__ float g_q[(size_t)Mn * En];
__device__ float g_k[(size_t)Mn * En];
__device__ float g_v[(size_t)Mn * En];
__device__ float g_attn[(size_t)Mn * En];

__device__ __forceinline__ float hi_part(float v) {
    // keep top 10 mantissa bits (tf32-exact under HW truncation); lo = v - hi exact
    return __uint_as_float(__float_as_uint(v) & 0xffffe000u);
}

__device__ __forceinline__ void split4(float4 v, float4& hi, float4& lo) {
    hi.x = hi_part(v.x); lo.x = v.x - hi.x;
    hi.y = hi_part(v.y); lo.y = v.y - hi.y;
    hi.z = hi_part(v.z); lo.z = v.z - hi.z;
    hi.w = hi_part(v.w); lo.w = v.w - hi.w;
}

// ---------------------------------------------------------------------------
// GEMM: C[M,1024] = (A[M,1024] @ W^T + bias) * alpha      (W is [1024,1024])
// 3xTF32: both operands split hi/lo, products hi*hi + hi*lo + lo*hi.
// wmma m16n16k8, block tile 128x64, BK=32, 256 threads.
// ---------------------------------------------------------------------------
__global__ __launch_bounds__(256) void gemm_xwt_kernel(
    const float* __restrict__ A, const float* __restrict__ W,
    const float* __restrict__ bias, float* __restrict__ C, float alpha)
{
    extern __shared__ float sm[];
    float* s_ahi = sm;             // 128 x 36
    float* s_alo = sm + 4608;      // 128 x 36
    float* s_bhi = sm + 9216;      // 64  x 36  (rows = n, cols = k)
    float* s_blo = sm + 11520;     // 64  x 36

    const int tid = threadIdx.x;
    const int wid = tid >> 5;
    const int wi  = wid & 3;      // row group of 32
    const int wj  = wid >> 2;     // col group of 32
    const int m0  = blockIdx.y * 128;
    const int n0  = blockIdx.x * 64;

    wmma::fragment<wmma::accumulator, 16, 16, 8, float> acc[2][2];
    #pragma unroll
    for (int i = 0; i < 2; i++)
        #pragma unroll
        for (int j = 0; j < 2; j++)
            wmma::fill_fragment(acc[i][j], 0.0f);

    const float* Ab = A + (size_t)m0 * En;
    const float* Wb = W + (size_t)n0 * En;

    for (int k0 = 0; k0 < En; k0 += 32) {
        #pragma unroll
        for (int i = tid; i < 1024; i += 256) {
            int r = i >> 3, c = i & 7;
            float4 v = *(const float4*)(Ab + (size_t)r * En + k0 + c * 4);
            float4 hi, lo; split4(v, hi, lo);
            *(float4*)(s_ahi + r * 36 + c * 4) = hi;
            *(float4*)(s_alo + r * 36 + c * 4) = lo;
        }
        #pragma unroll
        for (int i = tid; i < 512; i += 256) {
            int r = i >> 3, c = i & 7;
            float4 v = *(const float4*)(Wb + (size_t)r * En + k0 + c * 4);
            float4 hi, lo; split4(v, hi, lo);
            *(float4*)(s_bhi + r * 36 + c * 4) = hi;
            *(float4*)(s_blo + r * 36 + c * 4) = lo;
        }
        __syncthreads();

        #pragma unroll
        for (int kk = 0; kk < 4; kk++) {
            wmma::fragment<wmma::matrix_a, 16, 16, 8, wmma::precision::tf32, wmma::row_major> ahi[2], alo[2];
            wmma::fragment<wmma::matrix_b, 16, 16, 8, wmma::precision::tf32, wmma::col_major> bhi[2], blo[2];
            #pragma unroll
            for (int i = 0; i < 2; i++) {
                wmma::load_matrix_sync(ahi[i], s_ahi + (wi * 32 + i * 16) * 36 + kk * 8, 36);
                wmma::load_matrix_sync(alo[i], s_alo + (wi * 32 + i * 16) * 36 + kk * 8, 36);
            }
            #pragma unroll
            for (int j = 0; j < 2; j++) {
                wmma::load_matrix_sync(bhi[j], s_bhi + (wj * 32 + j * 16) * 36 + kk * 8, 36);
                wmma::load_matrix_sync(blo[j], s_blo + (wj * 32 + j * 16) * 36 + kk * 8, 36);
            }
            #pragma unroll
            for (int i = 0; i < 2; i++)
                #pragma unroll
                for (int j = 0; j < 2; j++) {
                    wmma::mma_sync(acc[i][j], ahi[i], bhi[j], acc[i][j]);
                    wmma::mma_sync(acc[i][j], ahi[i], blo[j], acc[i][j]);
                    wmma::mma_sync(acc[i][j], alo[i], bhi[j], acc[i][j]);
                }
        }
        __syncthreads();
    }

    // Epilogue: stage in smem (128*68 = 8704 floats fits in the 13824 tile area)
    float* csm = sm;
    #pragma unroll
    for (int i = 0; i < 2; i++)
        #pragma unroll
        for (int j = 0; j < 2; j++)
            wmma::store_matrix_sync(csm + (wi * 32 + i * 16) * 68 + (wj * 32 + j * 16),
                                    acc[i][j], 68, wmma::mem_row_major);
    __syncthreads();
    for (int i = tid; i < 2048; i += 256) {
        int r = i >> 4, c4 = i & 15;
        float4 v = *(float4*)(csm + r * 68 + c4 * 4);
        int n = n0 + c4 * 4;
        v.x = (v.x + bias[n + 0]) * alpha;
        v.y = (v.y + bias[n + 1]) * alpha;
        v.z = (v.z + bias[n + 2]) * alpha;
        v.w = (v.w + bias[n + 3]) * alpha;
        *(float4*)(C + (size_t)(m0 + r) * En + n) = v;
    }
}

// ---------------------------------------------------------------------------
// Attention: per block = 64 t-rows of one (b,h). Stream s in tiles of 64.
// No max-subtraction (scores bounded ~|6|): out = (sum exp(s)*V) / (sum exp).
// 3xTF32 on S (Q,K both split) and PV (P,V both split).
// padding_mask arrives as int32 (jax bool -> int32 serialization).
// ---------------------------------------------------------------------------
__global__ __launch_bounds__(256) void attn_kernel(
    const float* __restrict__ q, const float* __restrict__ k, const float* __restrict__ v,
    const float* __restrict__ bias, const int* __restrict__ mask,
    float* __restrict__ out)
{
    extern __shared__ float sm[];
    float* q_hi = sm;               // 64 x 72
    float* q_lo = sm + 4608;
    float* k_hi = sm + 2 * 4608;
    float* k_lo = sm + 3 * 4608;    // becomes P_lo after S is consumed
    float* v_hi = sm + 4 * 4608;
    float* v_lo = sm + 5 * 4608;
    float* sp   = sm + 6 * 4608;    // S -> P_hi -> O
    float* lsum = sm + 7 * 4608;    // 64
    int*   smk  = (int*)(sm + 7 * 4608 + 64);  // 64 mask values

    const int tid = threadIdx.x;
    const int wid = tid >> 5;
    const int wi  = wid >> 1;          // 0..3 : 16-row tile
    const int wj0 = (wid & 1) * 2;     // 0 or 2 : first of two 16-col tiles
    const int t0  = blockIdx.x * 64;
    const int bh  = blockIdx.y;
    const int b   = bh / Hn;
    const int h   = bh % Hn;

    // Load Q tile (64 x 64), split hi/lo
    for (int i = tid; i < 1024; i += 256) {
        int t = i >> 4, c4 = i & 15;
        float4 vq = *(const float4*)(q + ((size_t)(t0 + t) * Bn + b) * En + h * 64 + c4 * 4);
        float4 hi, lo; split4(vq, hi, lo);
        *(float4*)(q_hi + t * 72 + c4 * 4) = hi;
        *(float4*)(q_lo + t * 72 + c4 * 4) = lo;
    }
    if (tid < 64) lsum[tid] = 0.0f;

    wmma::fragment<wmma::accumulator, 16, 16, 8, float> oacc[2];
    wmma::fill_fragment(oacc[0], 0.0f);
    wmma::fill_fragment(oacc[1], 0.0f);

    const float* biasBH = bias + (size_t)bh * Tn * Tn;
    const int* maskB = mask + b * Tn;

    for (int s0 = 0; s0 < Tn; s0 += 64) {
        __syncthreads();   // previous iter's readers of k/v/sp tiles are done
        for (int i = tid; i < 1024; i += 256) {
            int s = i >> 4, c4 = i & 15;
            size_t base = ((size_t)(s0 + s) * Bn + b) * En + h * 64 + c4 * 4;
            float4 kv = *(const float4*)(k + base);
            float4 vv = *(const float4*)(v + base);
            float4 hi, lo;
            split4(kv, hi, lo);
            *(float4*)(k_hi + s * 72 + c4 * 4) = hi;
            *(float4*)(k_lo + s * 72 + c4 * 4) = lo;
            split4(vv, hi, lo);
            *(float4*)(v_hi + s * 72 + c4 * 4) = hi;
            *(float4*)(v_lo + s * 72 + c4 * 4) = lo;
        }
        if (tid < 64) smk[tid] = maskB[s0 + tid];
        __syncthreads();

        // S = Q @ K^T  (64x64), 3xTF32
        {
            wmma::fragment<wmma::accumulator, 16, 16, 8, float> sacc[2];
            wmma::fill_fragment(sacc[0], 0.0f);
            wmma::fill_fragment(sacc[1], 0.0f);
            #pragma unroll
            for (int kk = 0; kk < 8; kk++) {
                wmma::fragment<wmma::matrix_a, 16, 16, 8, wmma::precision::tf32, wmma::row_major> ah, al;
                wmma::load_matrix_sync(ah, q_hi + (wi * 16) * 72 + kk * 8, 72);
                wmma::load_matrix_sync(al, q_lo + (wi * 16) * 72 + kk * 8, 72);
                #pragma unroll
                for (int j = 0; j < 2; j++) {
                    wmma::fragment<wmma::matrix_b, 16, 16, 8, wmma::precision::tf32, wmma::col_major> bh_, bl_;
                    wmma::load_matrix_sync(bh_, k_hi + ((wj0 + j) * 16) * 72 + kk * 8, 72);
                    wmma::load_matrix_sync(bl_, k_lo + ((wj0 + j) * 16) * 72 + kk * 8, 72);
                    wmma::mma_sync(sacc[j], ah, bh_, sacc[j]);
                    wmma::mma_sync(sacc[j], ah, bl_, sacc[j]);
                    wmma::mma_sync(sacc[j], al, bh_, sacc[j]);
                }
            }
            wmma::store_matrix_sync(sp + (wi * 16) * 72 + wj0 * 16,       sacc[0], 72, wmma::mem_row_major);
            wmma::store_matrix_sync(sp + (wi * 16) * 72 + (wj0 + 1) * 16, sacc[1], 72, wmma::mem_row_major);
        }
        __syncthreads();

        // mask + bias + exp; write P_hi to sp, P_lo to k_lo (K consumed)
        for (int i = tid; i < 4096; i += 256) {
            int t = i >> 6, s = i & 63;
            float val = sp[t * 72 + s];
            if (smk[s] != 0) val = -1e-16f;
            val += biasBH[(size_t)(t0 + t) * Tn + (s0 + s)];
            float p = __expf(val);
            float hi = hi_part(p);
            sp[t * 72 + s]   = hi;
            k_lo[t * 72 + s] = p - hi;
        }
        __syncthreads();

        // row sums of P (hi + lo = exact p)
        if (tid < 64) {
            float a = 0.0f;
            #pragma unroll 8
            for (int s = 0; s < 64; s++) a += sp[tid * 72 + s] + k_lo[tid * 72 + s];
            lsum[tid] += a;
        }

        // O += P @ V, 3xTF32
        #pragma unroll
        for (int kk = 0; kk < 8; kk++) {
            wmma::fragment<wmma::matrix_a, 16, 16, 8, wmma::precision::tf32, wmma::row_major> ph, pl;
            wmma::load_matrix_sync(ph, sp   + (wi * 16) * 72 + kk * 8, 72);
            wmma::load_matrix_sync(pl, k_lo + (wi * 16) * 72 + kk * 8, 72);
            #pragma unroll
            for (int j = 0; j < 2; j++) {
                wmma::fragment<wmma::matrix_b, 16, 16, 8, wmma::precision::tf32, wmma::row_major> vh_, vl_;
                wmma::load_matrix_sync(vh_, v_hi + (kk * 8) * 72 + (wj0 + j) * 16, 72);
                wmma::load_matrix_sync(vl_, v_lo + (kk * 8) * 72 + (wj0 + j) * 16, 72);
                wmma::mma_sync(oacc[j], ph, vh_, oacc[j]);
                wmma::mma_sync(oacc[j], ph, vl_, oacc[j]);
                wmma::mma_sync(oacc[j], pl, vh_, oacc[j]);
            }
        }
    }

    __syncthreads();
    wmma::store_matrix_sync(sp + (wi * 16) * 72 + wj0 * 16,       oacc[0], 72, wmma::mem_row_major);
    wmma::store_matrix_sync(sp + (wi * 16) * 72 + (wj0 + 1) * 16, oacc[1], 72, wmma::mem_row_major);
    __syncthreads();
    for (int i = tid; i < 1024; i += 256) {
        int t = i >> 4, c4 = i & 15;
        float inv = 1.0f / lsum[t];
        float4 o = *(float4*)(sp + t * 72 + c4 * 4);
        o.x *= inv; o.y *= inv; o.z *= inv; o.w *= inv;
        *(float4*)(out + ((size_t)(t0 + t) * Bn + b) * En + h * 64 + c4 * 4) = o;
    }
}

// ---------------------------------------------------------------------------
extern "C" void kernel_launch(void* const* d_in, const int* in_sizes, int n_in,
                              void* d_out, int out_size)
{
    (void)in_sizes; (void)n_in; (void)out_size;
    const float* x  = (const float*)d_in[0];
    const int* mask = (const int*)d_in[1];     // jax bool -> int32 serialization
    const float* bias = (const float*)d_in[2];
    const float* Wq = (const float*)d_in[3];
    const float* bq = (const float*)d_in[4];
    const float* Wk = (const float*)d_in[5];
    const float* bk = (const float*)d_in[6];
    const float* Wv = (const float*)d_in[7];
    const float* bv = (const float*)d_in[8];
    const float* Wo = (const float*)d_in[9];
    const float* bo = (const float*)d_in[10];
    float* out = (float*)d_out;

    void *pq, *pk, *pv, *pa;
    cudaGetSymbolAddress(&pq, g_q);
    cudaGetSymbolAddress(&pk, g_k);
    cudaGetSymbolAddress(&pv, g_v);
    cudaGetSymbolAddress(&pa, g_attn);

    const int GEMM_SMEM = 13824 * 4;                       // 55296 B
    const int ATTN_SMEM = (7 * 4608 + 64 + 64) * 4;        // 129536 B
    cudaFuncSetAttribute(gemm_xwt_kernel, cudaFuncAttributeMaxDynamicSharedMemorySize, GEMM_SMEM);
    cudaFuncSetAttribute(attn_kernel, cudaFuncAttributeMaxDynamicSharedMemorySize, ATTN_SMEM);

    dim3 ggrid(En / 64, Mn / 128);   // (16, 32)
    gemm_xwt_kernel<<<ggrid, 256, GEMM_SMEM>>>(x, Wq, bq, (float*)pq, 0.125f);  // 64^-0.5
    gemm_xwt_kernel<<<ggrid, 256, GEMM_SMEM>>>(x, Wk, bk, (float*)pk, 1.0f);
    gemm_xwt_kernel<<<ggrid, 256, GEMM_SMEM>>>(x, Wv, bv, (float*)pv, 1.0f);

    dim3 agrid(Tn / 64, Bn * Hn);    // (32, 32)
    attn_kernel<<<agrid, 256, ATTN_SMEM>>>((const float*)pq, (const float*)pk,
                                           (const float*)pv, bias, mask, (float*)pa);

    gemm_xwt_kernel<<<ggrid, 256, GEMM_SMEM>>>((const float*)pa, Wo, bo, out, 1.0f);
}

// round 10
// speedup vs baseline: 1.4757x; 1.4757x over previous
#include <cuda_runtime.h>
#include <mma.h>
#include <cstdint>
#include <cstddef>

using namespace nvcuda;

constexpr int Tn  = 2048;
constexpr int Bn  = 2;
constexpr int En  = 1024;
constexpr int Hn  = 16;
constexpr int Mn  = Tn * Bn;   // 4096 rows for the projection GEMMs

// Scratch (allocation-free rule: __device__ globals)
__device__ float g_q[(size_t)Mn * En];
__device__ float g_k[(size_t)Mn * En];
__device__ float g_v[(size_t)Mn * En];
__device__ float g_attn[(size_t)Mn * En];

__device__ __forceinline__ float hi_part(float v) {
    // keep top 10 mantissa bits (tf32-exact under HW truncation); lo = v - hi exact
    return __uint_as_float(__float_as_uint(v) & 0xffffe000u);
}

__device__ __forceinline__ float rn_tf32(float v) {
    // round-to-nearest tf32 (unbiased, unlike HW truncation in the MMA path)
    uint32_t r;
    asm("cvt.rna.tf32.f32 %0, %1;" : "=r"(r) : "f"(v));
    return __uint_as_float(r);
}

__device__ __forceinline__ void split4(float4 v, float4& hi, float4& lo) {
    hi.x = hi_part(v.x); lo.x = v.x - hi.x;
    hi.y = hi_part(v.y); lo.y = v.y - hi.y;
    hi.z = hi_part(v.z); lo.z = v.z - hi.z;
    hi.w = hi_part(v.w); lo.w = v.w - hi.w;
}

// ---------------------------------------------------------------------------
// GEMM: C[M,1024] = (A[M,1024] @ W^T + bias) * alpha      (W is [1024,1024])
// 3xTF32: both operands split hi/lo, products hi*hi + hi*lo + lo*hi.
// wmma m16n16k8, block tile 128x64, BK=32, 256 threads.  (unchanged from R9)
// ---------------------------------------------------------------------------
__global__ __launch_bounds__(256) void gemm_xwt_kernel(
    const float* __restrict__ A, const float* __restrict__ W,
    const float* __restrict__ bias, float* __restrict__ C, float alpha)
{
    extern __shared__ float sm[];
    float* s_ahi = sm;             // 128 x 36
    float* s_alo = sm + 4608;      // 128 x 36
    float* s_bhi = sm + 9216;      // 64  x 36  (rows = n, cols = k)
    float* s_blo = sm + 11520;     // 64  x 36

    const int tid = threadIdx.x;
    const int wid = tid >> 5;
    const int wi  = wid & 3;      // row group of 32
    const int wj  = wid >> 2;     // col group of 32
    const int m0  = blockIdx.y * 128;
    const int n0  = blockIdx.x * 64;

    wmma::fragment<wmma::accumulator, 16, 16, 8, float> acc[2][2];
    #pragma unroll
    for (int i = 0; i < 2; i++)
        #pragma unroll
        for (int j = 0; j < 2; j++)
            wmma::fill_fragment(acc[i][j], 0.0f);

    const float* Ab = A + (size_t)m0 * En;
    const float* Wb = W + (size_t)n0 * En;

    for (int k0 = 0; k0 < En; k0 += 32) {
        #pragma unroll
        for (int i = tid; i < 1024; i += 256) {
            int r = i >> 3, c = i & 7;
            float4 v = *(const float4*)(Ab + (size_t)r * En + k0 + c * 4);
            float4 hi, lo; split4(v, hi, lo);
            *(float4*)(s_ahi + r * 36 + c * 4) = hi;
            *(float4*)(s_alo + r * 36 + c * 4) = lo;
        }
        #pragma unroll
        for (int i = tid; i < 512; i += 256) {
            int r = i >> 3, c = i & 7;
            float4 v = *(const float4*)(Wb + (size_t)r * En + k0 + c * 4);
            float4 hi, lo; split4(v, hi, lo);
            *(float4*)(s_bhi + r * 36 + c * 4) = hi;
            *(float4*)(s_blo + r * 36 + c * 4) = lo;
        }
        __syncthreads();

        #pragma unroll
        for (int kk = 0; kk < 4; kk++) {
            wmma::fragment<wmma::matrix_a, 16, 16, 8, wmma::precision::tf32, wmma::row_major> ahi[2], alo[2];
            wmma::fragment<wmma::matrix_b, 16, 16, 8, wmma::precision::tf32, wmma::col_major> bhi[2], blo[2];
            #pragma unroll
            for (int i = 0; i < 2; i++) {
                wmma::load_matrix_sync(ahi[i], s_ahi + (wi * 32 + i * 16) * 36 + kk * 8, 36);
                wmma::load_matrix_sync(alo[i], s_alo + (wi * 32 + i * 16) * 36 + kk * 8, 36);
            }
            #pragma unroll
            for (int j = 0; j < 2; j++) {
                wmma::load_matrix_sync(bhi[j], s_bhi + (wj * 32 + j * 16) * 36 + kk * 8, 36);
                wmma::load_matrix_sync(blo[j], s_blo + (wj * 32 + j * 16) * 36 + kk * 8, 36);
            }
            #pragma unroll
            for (int i = 0; i < 2; i++)
                #pragma unroll
                for (int j = 0; j < 2; j++) {
                    wmma::mma_sync(acc[i][j], ahi[i], bhi[j], acc[i][j]);
                    wmma::mma_sync(acc[i][j], ahi[i], blo[j], acc[i][j]);
                    wmma::mma_sync(acc[i][j], alo[i], bhi[j], acc[i][j]);
                }
        }
        __syncthreads();
    }

    // Epilogue: stage in smem (128*68 = 8704 floats fits in the tile area)
    float* csm = sm;
    #pragma unroll
    for (int i = 0; i < 2; i++)
        #pragma unroll
        for (int j = 0; j < 2; j++)
            wmma::store_matrix_sync(csm + (wi * 32 + i * 16) * 68 + (wj * 32 + j * 16),
                                    acc[i][j], 68, wmma::mem_row_major);
    __syncthreads();
    for (int i = tid; i < 2048; i += 256) {
        int r = i >> 4, c4 = i & 15;
        float4 v = *(float4*)(csm + r * 68 + c4 * 4);
        int n = n0 + c4 * 4;
        v.x = (v.x + bias[n + 0]) * alpha;
        v.y = (v.y + bias[n + 1]) * alpha;
        v.z = (v.z + bias[n + 2]) * alpha;
        v.w = (v.w + bias[n + 3]) * alpha;
        *(float4*)(C + (size_t)(m0 + r) * En + n) = v;
    }
}

// ---------------------------------------------------------------------------
// Attention: per block = 64 t-rows of one (b,h). Stream s in tiles of 64.
// No max-subtraction (scores bounded ~|6|): out = (sum exp(s)*V) / (sum exp).
// Precision: split-left + RN-right.
//   S  = (Q_hi + Q_lo) @ K_rn^T   : Q split exact, K pre-rounded RN tf32.
//   O += (P_hi + P_lo) @ V_rn     : P split exact, V pre-rounded RN tf32.
// 2 MMAs per product pair (was 3), 6 smem tiles (was 7) -> 111KB -> 2 CTA/SM.
// padding_mask arrives as int32 (jax bool -> int32 serialization).
// ---------------------------------------------------------------------------
__global__ __launch_bounds__(256, 2) void attn_kernel(
    const float* __restrict__ q, const float* __restrict__ k, const float* __restrict__ v,
    const float* __restrict__ bias, const int* __restrict__ mask,
    float* __restrict__ out)
{
    extern __shared__ float sm[];
    float* q_hi = sm;               // 64 x 72
    float* q_lo = sm + 4608;
    float* kt   = sm + 2 * 4608;    // K tile (RN tf32)
    float* vt   = sm + 3 * 4608;    // V tile (RN tf32)
    float* sp   = sm + 4 * 4608;    // S -> P_hi -> O
    float* plo  = sm + 5 * 4608;    // P_lo
    float* lsum = sm + 6 * 4608;    // 64
    int*   smk  = (int*)(sm + 6 * 4608 + 64);  // 64 mask values

    const int tid = threadIdx.x;
    const int wid = tid >> 5;
    const int wi  = wid >> 1;          // 0..3 : 16-row tile
    const int wj0 = (wid & 1) * 2;     // 0 or 2 : first of two 16-col tiles
    const int t0  = blockIdx.x * 64;
    const int bh  = blockIdx.y;
    const int b   = bh / Hn;
    const int h   = bh % Hn;

    // Load Q tile (64 x 64), split hi/lo (exact split)
    for (int i = tid; i < 1024; i += 256) {
        int t = i >> 4, c4 = i & 15;
        float4 vq = *(const float4*)(q + ((size_t)(t0 + t) * Bn + b) * En + h * 64 + c4 * 4);
        float4 hi, lo; split4(vq, hi, lo);
        *(float4*)(q_hi + t * 72 + c4 * 4) = hi;
        *(float4*)(q_lo + t * 72 + c4 * 4) = lo;
    }
    if (tid < 64) lsum[tid] = 0.0f;

    wmma::fragment<wmma::accumulator, 16, 16, 8, float> oacc[2];
    wmma::fill_fragment(oacc[0], 0.0f);
    wmma::fill_fragment(oacc[1], 0.0f);

    const float* biasBH = bias + (size_t)bh * Tn * Tn;
    const int* maskB = mask + b * Tn;

    for (int s0 = 0; s0 < Tn; s0 += 64) {
        __syncthreads();   // previous iter's readers of kt/vt/sp/plo are done
        for (int i = tid; i < 1024; i += 256) {
            int s = i >> 4, c4 = i & 15;
            size_t base = ((size_t)(s0 + s) * Bn + b) * En + h * 64 + c4 * 4;
            float4 kv = *(const float4*)(k + base);
            float4 vv = *(const float4*)(v + base);
            kv.x = rn_tf32(kv.x); kv.y = rn_tf32(kv.y);
            kv.z = rn_tf32(kv.z); kv.w = rn_tf32(kv.w);
            vv.x = rn_tf32(vv.x); vv.y = rn_tf32(vv.y);
            vv.z = rn_tf32(vv.z); vv.w = rn_tf32(vv.w);
            *(float4*)(kt + s * 72 + c4 * 4) = kv;
            *(float4*)(vt + s * 72 + c4 * 4) = vv;
        }
        if (tid < 64) smk[tid] = maskB[s0 + tid];
        __syncthreads();

        // S = Q @ K^T  (64x64): (Q_hi + Q_lo) x K_rn
        {
            wmma::fragment<wmma::accumulator, 16, 16, 8, float> sacc[2];
            wmma::fill_fragment(sacc[0], 0.0f);
            wmma::fill_fragment(sacc[1], 0.0f);
            #pragma unroll
            for (int kk = 0; kk < 8; kk++) {
                wmma::fragment<wmma::matrix_a, 16, 16, 8, wmma::precision::tf32, wmma::row_major> ah, al;
                wmma::load_matrix_sync(ah, q_hi + (wi * 16) * 72 + kk * 8, 72);
                wmma::load_matrix_sync(al, q_lo + (wi * 16) * 72 + kk * 8, 72);
                #pragma unroll
                for (int j = 0; j < 2; j++) {
                    wmma::fragment<wmma::matrix_b, 16, 16, 8, wmma::precision::tf32, wmma::col_major> bk_;
                    wmma::load_matrix_sync(bk_, kt + ((wj0 + j) * 16) * 72 + kk * 8, 72);
                    wmma::mma_sync(sacc[j], ah, bk_, sacc[j]);
                    wmma::mma_sync(sacc[j], al, bk_, sacc[j]);
                }
            }
            wmma::store_matrix_sync(sp + (wi * 16) * 72 + wj0 * 16,       sacc[0], 72, wmma::mem_row_major);
            wmma::store_matrix_sync(sp + (wi * 16) * 72 + (wj0 + 1) * 16, sacc[1], 72, wmma::mem_row_major);
        }
        __syncthreads();

        // mask + bias + exp; write P_hi to sp (in place), P_lo to plo
        for (int i = tid; i < 4096; i += 256) {
            int t = i >> 6, s = i & 63;
            float val = sp[t * 72 + s];
            if (smk[s] != 0) val = -1e-16f;
            val += biasBH[(size_t)(t0 + t) * Tn + (s0 + s)];
            float p = __expf(val);
            float hi = hi_part(p);
            sp[t * 72 + s]  = hi;
            plo[t * 72 + s] = p - hi;
        }
        __syncthreads();

        // row sums of P (hi + lo = exact p)
        if (tid < 64) {
            float a = 0.0f;
            #pragma unroll 8
            for (int s = 0; s < 64; s++) a += sp[tid * 72 + s] + plo[tid * 72 + s];
            lsum[tid] += a;
        }

        // O += P @ V: (P_hi + P_lo) x V_rn
        #pragma unroll
        for (int kk = 0; kk < 8; kk++) {
            wmma::fragment<wmma::matrix_a, 16, 16, 8, wmma::precision::tf32, wmma::row_major> ph, pl;
            wmma::load_matrix_sync(ph, sp  + (wi * 16) * 72 + kk * 8, 72);
            wmma::load_matrix_sync(pl, plo + (wi * 16) * 72 + kk * 8, 72);
            #pragma unroll
            for (int j = 0; j < 2; j++) {
                wmma::fragment<wmma::matrix_b, 16, 16, 8, wmma::precision::tf32, wmma::row_major> vv_;
                wmma::load_matrix_sync(vv_, vt + (kk * 8) * 72 + (wj0 + j) * 16, 72);
                wmma::mma_sync(oacc[j], ph, vv_, oacc[j]);
                wmma::mma_sync(oacc[j], pl, vv_, oacc[j]);
            }
        }
    }

    __syncthreads();
    wmma::store_matrix_sync(sp + (wi * 16) * 72 + wj0 * 16,       oacc[0], 72, wmma::mem_row_major);
    wmma::store_matrix_sync(sp + (wi * 16) * 72 + (wj0 + 1) * 16, oacc[1], 72, wmma::mem_row_major);
    __syncthreads();
    for (int i = tid; i < 1024; i += 256) {
        int t = i >> 4, c4 = i & 15;
        float inv = 1.0f / lsum[t];
        float4 o = *(float4*)(sp + t * 72 + c4 * 4);
        o.x *= inv; o.y *= inv; o.z *= inv; o.w *= inv;
        *(float4*)(out + ((size_t)(t0 + t) * Bn + b) * En + h * 64 + c4 * 4) = o;
    }
}

// ---------------------------------------------------------------------------
extern "C" void kernel_launch(void* const* d_in, const int* in_sizes, int n_in,
                              void* d_out, int out_size)
{
    (void)in_sizes; (void)n_in; (void)out_size;
    const float* x  = (const float*)d_in[0];
    const int* mask = (const int*)d_in[1];     // jax bool -> int32 serialization
    const float* bias = (const float*)d_in[2];
    const float* Wq = (const float*)d_in[3];
    const float* bq = (const float*)d_in[4];
    const float* Wk = (const float*)d_in[5];
    const float* bk = (const float*)d_in[6];
    const float* Wv = (const float*)d_in[7];
    const float* bv = (const float*)d_in[8];
    const float* Wo = (const float*)d_in[9];
    const float* bo = (const float*)d_in[10];
    float* out = (float*)d_out;

    void *pq, *pk, *pv, *pa;
    cudaGetSymbolAddress(&pq, g_q);
    cudaGetSymbolAddress(&pk, g_k);
    cudaGetSymbolAddress(&pv, g_v);
    cudaGetSymbolAddress(&pa, g_attn);

    const int GEMM_SMEM = 13824 * 4;                       // 55296 B
    const int ATTN_SMEM = (6 * 4608 + 64 + 64) * 4;        // 111104 B -> 2 CTA/SM
    cudaFuncSetAttribute(gemm_xwt_kernel, cudaFuncAttributeMaxDynamicSharedMemorySize, GEMM_SMEM);
    cudaFuncSetAttribute(attn_kernel, cudaFuncAttributeMaxDynamicSharedMemorySize, ATTN_SMEM);

    dim3 ggrid(En / 64, Mn / 128);   // (16, 32)
    gemm_xwt_kernel<<<ggrid, 256, GEMM_SMEM>>>(x, Wq, bq, (float*)pq, 0.125f);  // 64^-0.5
    gemm_xwt_kernel<<<ggrid, 256, GEMM_SMEM>>>(x, Wk, bk, (float*)pk, 1.0f);
    gemm_xwt_kernel<<<ggrid, 256, GEMM_SMEM>>>(x, Wv, bv, (float*)pv, 1.0f);

    dim3 agrid(Tn / 64, Bn * Hn);    // (32, 32)
    attn_kernel<<<agrid, 256, ATTN_SMEM>>>((const float*)pq, (const float*)pk,
                                           (const float*)pv, bias, mask, (float*)pa);

    gemm_xwt_kernel<<<ggrid, 256, GEMM_SMEM>>>((const float*)pa, Wo, bo, out, 1.0f);
}